// round 16
// baseline (speedup 1.0000x reference)
#include <cuda_runtime.h>

#define EPSV 1e-5f

// ---------------- scratch (static device globals; no runtime alloc) -------------
__device__ float g_y[64*256*25];               // mean over T
__device__ float g_qkv[64*512*25];             // raw qkv projection
__device__ float g_qsum[512], g_qsq[512];
__device__ float g_stk[64*8*2500];             // qk/qr/kr packed float4 (a,b,c,0)
__device__ float g_ssum[24], g_ssq[24];
__device__ float2 g_so2[64*256*25];            // (sv,se) pairs, [(n*256+cout)*25+i]
__device__ float g_osum[512], g_osq[512];

// ---------------- K1: y[n,c,v] = mean_t x[n,c,t,v]  (16 slabs/block, ldcs) ------
__global__ void __launch_bounds__(400) k1_mean(const float* __restrict__ x) {
    __shared__ float red[4][1600];
    int tid = threadIdx.x;
    if (blockIdx.x == 0) {
        for (int i = tid; i < 512; i += 400) { g_qsum[i]=0.f; g_qsq[i]=0.f; g_osum[i]=0.f; g_osq[i]=0.f; }
        if (tid < 24) { g_ssum[tid]=0.f; g_ssq[tid]=0.f; }
    }
    int sg = tid / 100, p = tid % 100;
    int base = blockIdx.x * 16 + sg;               // this thread's slabs: base+{0,4,8,12}
    const float4* xp0 = (const float4*)(x + (base +  0) * 1600) + p;
    const float4* xp1 = (const float4*)(x + (base +  4) * 1600) + p;
    const float4* xp2 = (const float4*)(x + (base +  8) * 1600) + p;
    const float4* xp3 = (const float4*)(x + (base + 12) * 1600) + p;
    float4 a0=__ldcs(xp0),a1=__ldcs(xp0+100),a2=__ldcs(xp0+200),a3=__ldcs(xp0+300);
    float4 b0=__ldcs(xp1),b1=__ldcs(xp1+100),b2=__ldcs(xp1+200),b3=__ldcs(xp1+300);
    float4 sa = make_float4(a0.x+a1.x+a2.x+a3.x, a0.y+a1.y+a2.y+a3.y,
                            a0.z+a1.z+a2.z+a3.z, a0.w+a1.w+a2.w+a3.w);
    float4 sb = make_float4(b0.x+b1.x+b2.x+b3.x, b0.y+b1.y+b2.y+b3.y,
                            b0.z+b1.z+b2.z+b3.z, b0.w+b1.w+b2.w+b3.w);
    ((float4*)red[0])[sg*100 + p] = sa;
    ((float4*)red[1])[sg*100 + p] = sb;
    float4 c0=__ldcs(xp2),c1=__ldcs(xp2+100),c2=__ldcs(xp2+200),c3=__ldcs(xp2+300);
    float4 d0=__ldcs(xp3),d1=__ldcs(xp3+100),d2=__ldcs(xp3+200),d3=__ldcs(xp3+300);
    float4 sc4 = make_float4(c0.x+c1.x+c2.x+c3.x, c0.y+c1.y+c2.y+c3.y,
                             c0.z+c1.z+c2.z+c3.z, c0.w+c1.w+c2.w+c3.w);
    float4 sd4 = make_float4(d0.x+d1.x+d2.x+d3.x, d0.y+d1.y+d2.y+d3.y,
                             d0.z+d1.z+d2.z+d3.z, d0.w+d1.w+d2.w+d3.w);
    ((float4*)red[2])[sg*100 + p] = sc4;
    ((float4*)red[3])[sg*100 + p] = sd4;
    __syncthreads();
    if (p < 25) {
        float t0=0.f, t1=0.f, t2=0.f, t3=0.f;
#pragma unroll
        for (int r = 0; r < 16; r++) {
            t0 += red[0][sg*400 + p + 25*r];
            t1 += red[1][sg*400 + p + 25*r];
            t2 += red[2][sg*400 + p + 25*r];
            t3 += red[3][sg*400 + p + 25*r];
        }
        g_y[(base +  0)*25 + p] = t0 * (1.0f/64.0f);
        g_y[(base +  4)*25 + p] = t1 * (1.0f/64.0f);
        g_y[(base +  8)*25 + p] = t2 * (1.0f/64.0f);
        g_y[(base + 12)*25 + p] = t3 * (1.0f/64.0f);
    }
}

// ---------------- K2: qkv projection; 512 blocks, 4 threads per o over c-quarters
__global__ void __launch_bounds__(256) k2_qkv(const float* __restrict__ w) {
    __shared__ __align__(16) float ysm[256*28];
    __shared__ float wsm[16][65];                   // [c-idx][o], row pad 65
    __shared__ float red[3][64*29];                 // partials from cq=1..3, stride 29
    int tid = threadIdx.x;
    int n = blockIdx.x >> 3, eighth = blockIdx.x & 7;
    int obase = eighth * 64;
    int olocal = tid & 63, cq = tid >> 6;           // cq in 0..3, 64 c's each

    for (int i = tid; i < 256*28; i += 256) ysm[i] = 0.f;
    __syncthreads();
    const float* yb = g_y + n * (256*25);
    for (int i = tid; i < 256*25; i += 256) { int c = i/25, v = i - c*25; ysm[c*28 + v] = yb[i]; }

    unsigned long long acc[14];
#pragma unroll
    for (int q = 0; q < 14; q++) acc[q] = 0ull;

    int ol_l = tid >> 2, cq_l = tid & 3;            // load-side mapping (float4 each)
    for (int r = 0; r < 16; r++) {
        __syncthreads();
        float4 wv4 = *(const float4*)(w + (obase + ol_l)*256 + cq_l*64 + r*4);
        wsm[cq_l*4 + 0][ol_l] = wv4.x;
        wsm[cq_l*4 + 1][ol_l] = wv4.y;
        wsm[cq_l*4 + 2][ol_l] = wv4.z;
        wsm[cq_l*4 + 3][ol_l] = wv4.w;
        __syncthreads();
#pragma unroll
        for (int k = 0; k < 4; k++) {
            int c = cq*64 + r*4 + k;
            float wv = wsm[cq*4 + k][olocal];
            unsigned long long w2; asm("mov.b64 %0,{%1,%1};" : "=l"(w2) : "f"(wv));
            const ulonglong2* yr = (const ulonglong2*)(ysm + c*28);
#pragma unroll
            for (int q = 0; q < 7; q++) {
                ulonglong2 yv = yr[q];
                asm("fma.rn.f32x2 %0,%1,%2,%0;" : "+l"(acc[2*q])   : "l"(w2), "l"(yv.x));
                asm("fma.rn.f32x2 %0,%1,%2,%0;" : "+l"(acc[2*q+1]) : "l"(w2), "l"(yv.y));
            }
        }
    }
    float vals[28];
#pragma unroll
    for (int q = 0; q < 14; q++)
        asm("mov.b64 {%0,%1},%2;" : "=f"(vals[2*q]), "=f"(vals[2*q+1]) : "l"(acc[q]));

    if (cq > 0) {
#pragma unroll
        for (int v = 0; v < 25; v++) red[cq-1][olocal*29 + v] = vals[v];
    }
    __syncthreads();
    if (cq == 0) {
        int o = obase + olocal;
        float s = 0.f, sq = 0.f;
        float* qb = g_qkv + n*(512*25) + o*25;
#pragma unroll
        for (int v = 0; v < 25; v++) {
            float q = vals[v] + red[0][olocal*29 + v] + red[1][olocal*29 + v] + red[2][olocal*29 + v];
            qb[v] = q; s += q; sq += q*q;
        }
        atomicAdd(&g_qsum[o], s);
        atomicAdd(&g_qsq[o], sq);
    }
}

// ---------------- K4: {qk,qr,kr}; 2 blocks per (n,g), ~313 elements each --------
__global__ void __launch_bounds__(512) k4_sim(const float* __restrict__ rel,
                                              const float* __restrict__ qg,
                                              const float* __restrict__ qbb) {
    __shared__ float qs[400], ks[400], rs[1568];
    __shared__ float sc_[32], bi_[32];
    __shared__ float ssum[3], ssq[3];
    int tid = threadIdx.x;
    int ng = blockIdx.x >> 1, he = blockIdx.x & 1;  // element-half
    int n = ng >> 3, g = ng & 7;
    int gb = g * 64;
    if (tid < 32) {
        int ch = gb + tid;
        float m = g_qsum[ch] * (1.f/1600.f);
        float var = g_qsq[ch] * (1.f/1600.f) - m*m;
        float s = rsqrtf(var + EPSV) * qg[ch];
        sc_[tid] = s; bi_[tid] = qbb[ch] - m*s;
    }
    if (tid >= 64 && tid < 67) { ssum[tid-64] = 0.f; ssq[tid-64] = 0.f; }
    __syncthreads();
    const float* qkvb = g_qkv + n*12800 + gb*25;
    for (int i = tid; i < 400; i += 512) { int c = i/25; qs[i] = qkvb[i]     *sc_[c]    + bi_[c]; }
    for (int i = tid; i < 400; i += 512) { int c = i/25; ks[i] = qkvb[400+i] *sc_[16+c] + bi_[16+c]; }
    for (int i = tid; i < 1568; i += 512) rs[i] = rel[i];
    __syncthreads();

    float sa=0.f, qa=0.f, sb2=0.f, qb2=0.f, sc2=0.f, qc2=0.f;
    float4* ob4 = (float4*)(g_stk + ng * 2500);
    int e0 = he * 313, e1 = he ? 625 : 313;
    for (int e = e0 + tid; e < e1; e += 512) {
        int i = e/25, j = e - i*25;
        float a=0.f, b=0.f, c2=0.f;
        int di = i - j + 24, dj = j - i + 24;
#pragma unroll
        for (int c = 0; c < 16; c++) {
            float qv = qs[c*25 + i], kv = ks[c*25 + j];
            a  += qv * kv;
            b  += qv * rs[c*49 + di];
            c2 += kv * rs[(16+c)*49 + dj];
        }
        ob4[e] = make_float4(a, b, c2, 0.f);
        sa += a; qa += a*a; sb2 += b; qb2 += b*b; sc2 += c2; qc2 += c2*c2;
    }
#pragma unroll
    for (int d = 16; d > 0; d >>= 1) {
        sa  += __shfl_xor_sync(0xffffffffu, sa,  d);
        qa  += __shfl_xor_sync(0xffffffffu, qa,  d);
        sb2 += __shfl_xor_sync(0xffffffffu, sb2, d);
        qb2 += __shfl_xor_sync(0xffffffffu, qb2, d);
        sc2 += __shfl_xor_sync(0xffffffffu, sc2, d);
        qc2 += __shfl_xor_sync(0xffffffffu, qc2, d);
    }
    if ((tid & 31) == 0) {
        atomicAdd(&ssum[0], sa);  atomicAdd(&ssq[0], qa);
        atomicAdd(&ssum[1], sb2); atomicAdd(&ssq[1], qb2);
        atomicAdd(&ssum[2], sc2); atomicAdd(&ssq[2], qc2);
    }
    __syncthreads();
    if (tid < 3) { atomicAdd(&g_ssum[tid*8 + g], ssum[tid]); atomicAdd(&g_ssq[tid*8 + g], ssq[tid]); }
}

// ---------------- K6: softmax + sv/sve; conflict-free transposed fills ----------
__global__ void __launch_bounds__(512) k6_attn(const float* __restrict__ rel,
                                               const float* __restrict__ qg,
                                               const float* __restrict__ qbb,
                                               const float* __restrict__ sg,
                                               const float* __restrict__ sbb) {
    __shared__ float sim[25*27];                   // stride 27: gcd(27,32)=1
    __shared__ __align__(16) float vs_t[25*32];    // [j][c]
    __shared__ __align__(16) float rv_t[49*32];    // [d][c]
    __shared__ float rinv[25];
    __shared__ float svsh[800], sesh[800];
    __shared__ float vsc[32], vbi[32], ssc[3], sbi[3];
    int tid = threadIdx.x;
    int n = blockIdx.x >> 3, g = blockIdx.x & 7;
    int gb = g * 64;

    if (tid < 32) {                                 // BN finalize for 32 v channels
        int ch = gb + 32 + tid;
        float m = g_qsum[ch] * (1.f/1600.f);
        float var = g_qsq[ch] * (1.f/1600.f) - m*m;
        float s = rsqrtf(var + EPSV) * qg[ch];
        vsc[tid] = s; vbi[tid] = qbb[ch] - m*s;
    } else if (tid < 35) {                          // sim BN finalize (3 channels)
        int t2 = tid - 32, ch = t2*8 + g;
        float m = g_ssum[ch] * (1.f/40000.f);
        float var = g_ssq[ch] * (1.f/40000.f) - m*m;
        float s = rsqrtf(var + EPSV) * sg[ch];
        ssc[t2] = s; sbi[t2] = sbb[ch] - m*s;
    }
    __syncthreads();

    // transposed fills: c = i&31 fast -> consecutive STS addresses (no conflicts)
    const float* qkvb = g_qkv + n*12800 + (gb + 32)*25;
    for (int i = tid; i < 800; i += 512) {          // 800 = 25*32
        int j = i >> 5, c = i & 31;
        vs_t[j*32 + c] = qkvb[c*25 + j]*vsc[c] + vbi[c];
    }
    const float* relv = rel + 32*49;
    for (int i = tid; i < 1568; i += 512) {         // 1568 = 49*32
        int d = i >> 5, c = i & 31;
        rv_t[d*32 + c] = relv[c*49 + d];
    }

    // single exp pass; BN'd logits are O(few sigma) so no max shift needed
    const float4* sb4 = (const float4*)(g_stk + blockIdx.x * 2500);
    for (int e = tid; e < 625; e += 512) {
        int i = e/25, j = e - i*25;
        float4 t = sb4[e];
        float s = t.x*ssc[0] + sbi[0] + t.y*ssc[1] + sbi[1] + t.z*ssc[2] + sbi[2];
        sim[i*27 + j] = __expf(s);
    }
    __syncthreads();
    if (tid < 25) {                                 // serial row sums (no atomics)
        float s = 0.f;
#pragma unroll
        for (int j = 0; j < 25; j++) s += sim[tid*27 + j];
        rinv[tid] = 1.f / s;
    }
    __syncthreads();

    // 400 work items: (cpair 0..15, i 0..24); stage results in smem only
    if (tid < 400) {
        int cp = tid & 15, i = tid >> 4;
        float sv0=0.f, sv1=0.f, se0=0.f, se1=0.f;
#pragma unroll
        for (int j = 0; j < 25; j++) {
            float wv = sim[i*27 + j];
            float2 v = ((const float2*)(vs_t + j*32))[cp];
            float2 r = ((const float2*)(rv_t + (i - j + 24)*32))[cp];
            sv0 += wv*v.x; sv1 += wv*v.y;
            se0 += wv*r.x; se1 += wv*r.y;
        }
        float ri = rinv[i];
        sv0 *= ri; sv1 *= ri; se0 *= ri; se1 *= ri;
        int c0 = 2*cp, c1 = c0 + 1;
        svsh[c0*25 + i] = sv0; sesh[c0*25 + i] = se0;
        svsh[c1*25 + i] = sv1; sesh[c1*25 + i] = se1;
    }
    __syncthreads();
    // coalesced float2 stores: cout = g*32 + c, idx = c*25 + i
    {
        float2* sob2 = g_so2 + (n*256 + g*32)*25;
        for (int idx = tid; idx < 800; idx += 512)
            sob2[idx] = make_float2(svsh[idx], sesh[idx]);
    }
    if (tid < 64) {
        int c = tid >> 1;
        const float* src = (tid & 1) ? (sesh + c*25) : (svsh + c*25);
        float s = 0.f, sq = 0.f;
#pragma unroll
        for (int i = 0; i < 25; i++) { float v = src[i]; s += v; sq += v*v; }
        atomicAdd(&g_osum[gb + tid], s);
        atomicAdd(&g_osq[gb + tid], sq);
    }
}

// ---------------- K8: out = x*(1+sigmoid(o));  ldcs/stcs, 16-deep load batch ----
__global__ void __launch_bounds__(400) k8_out(const float* __restrict__ x,
                                              float* __restrict__ out,
                                              const float* __restrict__ og,
                                              const float* __restrict__ ob) {
    __shared__ float msh[16][25];
    int tid = threadIdx.x;
    int sg = tid / 100, p = tid % 100;
    int base = blockIdx.x * 16 + sg;               // this group's slabs: base+4w, w=0..3
    {   // gate: 400 threads <-> 16 slabs x 25 lanes, exactly one each
        int w = p / 25, pv = p % 25;
        int slab = base + 4*w;
        int n = slab >> 8, c = slab & 255;
        int ch0 = 2*c, ch1 = ch0 + 1;
        float m0 = g_osum[ch0] * (1.f/1600.f);
        float v0 = g_osq[ch0] * (1.f/1600.f) - m0*m0;
        float sc0 = rsqrtf(v0 + EPSV) * og[ch0];
        float b0 = ob[ch0] - m0*sc0;
        float m1 = g_osum[ch1] * (1.f/1600.f);
        float v1 = g_osq[ch1] * (1.f/1600.f) - m1*m1;
        float sc1 = rsqrtf(v1 + EPSV) * og[ch1];
        float b1 = ob[ch1] - m1*sc1;
        float2 t2 = g_so2[(n*256 + c)*25 + pv];
        float t = (t2.x*sc0 + b0) + (t2.y*sc1 + b1);
        msh[sg*4 + w][pv] = 1.f + 1.f/(1.f + expf(-t));
    }
    __syncthreads();
    int f0 = 4*p;
    int i0 = f0 % 25, i1 = (f0+1) % 25, i2 = (f0+2) % 25, i3 = (f0+3) % 25;
    const float4* pa = (const float4*)(x + (base +  0)*1600) + p;
    const float4* pb = (const float4*)(x + (base +  4)*1600) + p;
    const float4* pc = (const float4*)(x + (base +  8)*1600) + p;
    const float4* pd = (const float4*)(x + (base + 12)*1600) + p;
    float4 a0=__ldcs(pa),a1=__ldcs(pa+100),a2=__ldcs(pa+200),a3=__ldcs(pa+300);
    float4 b0=__ldcs(pb),b1=__ldcs(pb+100),b2=__ldcs(pb+200),b3=__ldcs(pb+300);
    float4 c0=__ldcs(pc),c1=__ldcs(pc+100),c2=__ldcs(pc+200),c3=__ldcs(pc+300);
    float4 d0=__ldcs(pd),d1=__ldcs(pd+100),d2=__ldcs(pd+200),d3=__ldcs(pd+300);
    const float* mA = msh[sg*4 + 0];
    const float* mB = msh[sg*4 + 1];
    const float* mC = msh[sg*4 + 2];
    const float* mD = msh[sg*4 + 3];
    float A0=mA[i0],A1=mA[i1],A2=mA[i2],A3=mA[i3];
    float B0=mB[i0],B1=mB[i1],B2=mB[i2],B3=mB[i3];
    float C0=mC[i0],C1=mC[i1],C2=mC[i2],C3=mC[i3];
    float D0=mD[i0],D1=mD[i1],D2=mD[i2],D3=mD[i3];
    float4* oa = (float4*)(out + (base +  0)*1600) + p;
    float4* obp= (float4*)(out + (base +  4)*1600) + p;
    float4* oc = (float4*)(out + (base +  8)*1600) + p;
    float4* od = (float4*)(out + (base + 12)*1600) + p;
    __stcs(oa,     make_float4(a0.x*A0, a0.y*A1, a0.z*A2, a0.w*A3));
    __stcs(oa+100, make_float4(a1.x*A0, a1.y*A1, a1.z*A2, a1.w*A3));
    __stcs(oa+200, make_float4(a2.x*A0, a2.y*A1, a2.z*A2, a2.w*A3));
    __stcs(oa+300, make_float4(a3.x*A0, a3.y*A1, a3.z*A2, a3.w*A3));
    __stcs(obp,     make_float4(b0.x*B0, b0.y*B1, b0.z*B2, b0.w*B3));
    __stcs(obp+100, make_float4(b1.x*B0, b1.y*B1, b1.z*B2, b1.w*B3));
    __stcs(obp+200, make_float4(b2.x*B0, b2.y*B1, b2.z*B2, b2.w*B3));
    __stcs(obp+300, make_float4(b3.x*B0, b3.y*B1, b3.z*B2, b3.w*B3));
    __stcs(oc,     make_float4(c0.x*C0, c0.y*C1, c0.z*C2, c0.w*C3));
    __stcs(oc+100, make_float4(c1.x*C0, c1.y*C1, c1.z*C2, c1.w*C3));
    __stcs(oc+200, make_float4(c2.x*C0, c2.y*C1, c2.z*C2, c2.w*C3));
    __stcs(oc+300, make_float4(c3.x*C0, c3.y*C1, c3.z*C2, c3.w*C3));
    __stcs(od,     make_float4(d0.x*D0, d0.y*D1, d0.z*D2, d0.w*D3));
    __stcs(od+100, make_float4(d1.x*D0, d1.y*D1, d1.z*D2, d1.w*D3));
    __stcs(od+200, make_float4(d2.x*D0, d2.y*D1, d2.z*D2, d2.w*D3));
    __stcs(od+300, make_float4(d3.x*D0, d3.y*D1, d3.z*D2, d3.w*D3));
}

// ---------------- launch ---------------------------------------------------------
extern "C" void kernel_launch(void* const* d_in, const int* in_sizes, int n_in,
                              void* d_out, int out_size) {
    const float* x   = (const float*)d_in[0];
    const float* w   = (const float*)d_in[1];
    const float* rel = (const float*)d_in[2];
    const float* qg  = (const float*)d_in[3];
    const float* qb  = (const float*)d_in[4];
    const float* sg  = (const float*)d_in[5];
    const float* sbb = (const float*)d_in[6];
    const float* og  = (const float*)d_in[7];
    const float* ob  = (const float*)d_in[8];
    float* out = (float*)d_out;

    k1_mean<<<1024, 400>>>(x);
    k2_qkv<<<512, 256>>>(w);
    k4_sim<<<1024, 512>>>(rel, qg, qb);
    k6_attn<<<512, 512>>>(rel, qg, qb, sg, sbb);
    k8_out<<<1024, 400>>>(x, out, og, ob);
}

// round 17
// speedup vs baseline: 1.0639x; 1.0639x over previous
#include <cuda_runtime.h>

#define EPSV 1e-5f

// ---------------- scratch (static device globals; no runtime alloc) -------------
__device__ float g_y[64*256*25];               // mean over T
__device__ float g_qkv[64*512*25];             // raw qkv projection
__device__ float g_qsum[512], g_qsq[512];
__device__ float g_stk[64*8*2500];             // qk/qr/kr packed float4 (a,b,c,0)
__device__ float g_ssum[24], g_ssq[24];
__device__ float2 g_so2[64*256*25];            // (sv,se) pairs, [(n*256+cout)*25+i]
__device__ float g_osum[512], g_osq[512];

// ---------------- K1: y[n,c,v] = mean_t x[n,c,t,v]  (16 slabs/block, ldcs) ------
__global__ void __launch_bounds__(400) k1_mean(const float* __restrict__ x) {
    __shared__ float red[4][1600];
    int tid = threadIdx.x;
    if (blockIdx.x == 0) {
        for (int i = tid; i < 512; i += 400) { g_qsum[i]=0.f; g_qsq[i]=0.f; g_osum[i]=0.f; g_osq[i]=0.f; }
        if (tid < 24) { g_ssum[tid]=0.f; g_ssq[tid]=0.f; }
    }
    int sg = tid / 100, p = tid % 100;
    int base = blockIdx.x * 16 + sg;               // this thread's slabs: base+{0,4,8,12}
    const float4* xp0 = (const float4*)(x + (base +  0) * 1600) + p;
    const float4* xp1 = (const float4*)(x + (base +  4) * 1600) + p;
    const float4* xp2 = (const float4*)(x + (base +  8) * 1600) + p;
    const float4* xp3 = (const float4*)(x + (base + 12) * 1600) + p;
    float4 a0=__ldcs(xp0),a1=__ldcs(xp0+100),a2=__ldcs(xp0+200),a3=__ldcs(xp0+300);
    float4 b0=__ldcs(xp1),b1=__ldcs(xp1+100),b2=__ldcs(xp1+200),b3=__ldcs(xp1+300);
    float4 sa = make_float4(a0.x+a1.x+a2.x+a3.x, a0.y+a1.y+a2.y+a3.y,
                            a0.z+a1.z+a2.z+a3.z, a0.w+a1.w+a2.w+a3.w);
    float4 sb = make_float4(b0.x+b1.x+b2.x+b3.x, b0.y+b1.y+b2.y+b3.y,
                            b0.z+b1.z+b2.z+b3.z, b0.w+b1.w+b2.w+b3.w);
    ((float4*)red[0])[sg*100 + p] = sa;
    ((float4*)red[1])[sg*100 + p] = sb;
    float4 c0=__ldcs(xp2),c1=__ldcs(xp2+100),c2=__ldcs(xp2+200),c3=__ldcs(xp2+300);
    float4 d0=__ldcs(xp3),d1=__ldcs(xp3+100),d2=__ldcs(xp3+200),d3=__ldcs(xp3+300);
    float4 sc4 = make_float4(c0.x+c1.x+c2.x+c3.x, c0.y+c1.y+c2.y+c3.y,
                             c0.z+c1.z+c2.z+c3.z, c0.w+c1.w+c2.w+c3.w);
    float4 sd4 = make_float4(d0.x+d1.x+d2.x+d3.x, d0.y+d1.y+d2.y+d3.y,
                             d0.z+d1.z+d2.z+d3.z, d0.w+d1.w+d2.w+d3.w);
    ((float4*)red[2])[sg*100 + p] = sc4;
    ((float4*)red[3])[sg*100 + p] = sd4;
    __syncthreads();
    if (p < 25) {
        float t0=0.f, t1=0.f, t2=0.f, t3=0.f;
#pragma unroll
        for (int r = 0; r < 16; r++) {
            t0 += red[0][sg*400 + p + 25*r];
            t1 += red[1][sg*400 + p + 25*r];
            t2 += red[2][sg*400 + p + 25*r];
            t3 += red[3][sg*400 + p + 25*r];
        }
        g_y[(base +  0)*25 + p] = t0 * (1.0f/64.0f);
        g_y[(base +  4)*25 + p] = t1 * (1.0f/64.0f);
        g_y[(base +  8)*25 + p] = t2 * (1.0f/64.0f);
        g_y[(base + 12)*25 + p] = t3 * (1.0f/64.0f);
    }
}

// ---------------- K2: qkv projection; 512 blocks, direct-w (no staging/barriers) -
__global__ void __launch_bounds__(256) k2_qkv(const float* __restrict__ w) {
    __shared__ __align__(16) float ysm[256*28];
    __shared__ float red[3][64*29];                 // partials from cq=1..3, stride 29
    int tid = threadIdx.x;
    int n = blockIdx.x >> 3, eighth = blockIdx.x & 7;
    int obase = eighth * 64;
    int olocal = tid & 63, cq = tid >> 6;           // cq in 0..3, 64 c's each

    for (int i = tid; i < 256*28; i += 256) ysm[i] = 0.f;
    __syncthreads();
    const float* yb = g_y + n * (256*25);
    for (int i = tid; i < 256*25; i += 256) { int c = i/25, v = i - c*25; ysm[c*28 + v] = yb[i]; }
    __syncthreads();

    unsigned long long acc[14];
#pragma unroll
    for (int q = 0; q < 14; q++) acc[q] = 0ull;

    // this thread's 64 w coefficients: row (obase+olocal), cols [cq*64, cq*64+64)
    const float4* wp = (const float4*)(w + (obase + olocal)*256 + cq*64);
#pragma unroll 4
    for (int r = 0; r < 16; r++) {
        float4 w4 = __ldg(wp + r);
#pragma unroll
        for (int k = 0; k < 4; k++) {
            int c = cq*64 + r*4 + k;
            float wv = (k == 0) ? w4.x : (k == 1) ? w4.y : (k == 2) ? w4.z : w4.w;
            unsigned long long w2; asm("mov.b64 %0,{%1,%1};" : "=l"(w2) : "f"(wv));
            const ulonglong2* yr = (const ulonglong2*)(ysm + c*28);
#pragma unroll
            for (int q = 0; q < 7; q++) {
                ulonglong2 yv = yr[q];
                asm("fma.rn.f32x2 %0,%1,%2,%0;" : "+l"(acc[2*q])   : "l"(w2), "l"(yv.x));
                asm("fma.rn.f32x2 %0,%1,%2,%0;" : "+l"(acc[2*q+1]) : "l"(w2), "l"(yv.y));
            }
        }
    }
    float vals[28];
#pragma unroll
    for (int q = 0; q < 14; q++)
        asm("mov.b64 {%0,%1},%2;" : "=f"(vals[2*q]), "=f"(vals[2*q+1]) : "l"(acc[q]));

    if (cq > 0) {
#pragma unroll
        for (int v = 0; v < 25; v++) red[cq-1][olocal*29 + v] = vals[v];
    }
    __syncthreads();
    if (cq == 0) {
        int o = obase + olocal;
        float s = 0.f, sq = 0.f;
        float* qb = g_qkv + n*(512*25) + o*25;
#pragma unroll
        for (int v = 0; v < 25; v++) {
            float q = vals[v] + red[0][olocal*29 + v] + red[1][olocal*29 + v] + red[2][olocal*29 + v];
            qb[v] = q; s += q; sq += q*q;
        }
        atomicAdd(&g_qsum[o], s);
        atomicAdd(&g_qsq[o], sq);
    }
}

// ---------------- K4: {qk,qr,kr} per (n,g), 512 threads (R15 proven) ------------
__global__ void __launch_bounds__(512) k4_sim(const float* __restrict__ rel,
                                              const float* __restrict__ qg,
                                              const float* __restrict__ qbb) {
    __shared__ float qs[400], ks[400], rs[1568];
    __shared__ float sc_[32], bi_[32];
    __shared__ float ssum[3], ssq[3];
    int tid = threadIdx.x;
    int n = blockIdx.x >> 3, g = blockIdx.x & 7;
    int gb = g * 64;
    if (tid < 32) {
        int ch = gb + tid;
        float m = g_qsum[ch] * (1.f/1600.f);
        float var = g_qsq[ch] * (1.f/1600.f) - m*m;
        float s = rsqrtf(var + EPSV) * qg[ch];
        sc_[tid] = s; bi_[tid] = qbb[ch] - m*s;
    }
    if (tid >= 64 && tid < 67) { ssum[tid-64] = 0.f; ssq[tid-64] = 0.f; }
    __syncthreads();
    const float* qkvb = g_qkv + n*12800 + gb*25;
    for (int i = tid; i < 400; i += 512) { int c = i/25; qs[i] = qkvb[i]     *sc_[c]    + bi_[c]; }
    for (int i = tid; i < 400; i += 512) { int c = i/25; ks[i] = qkvb[400+i] *sc_[16+c] + bi_[16+c]; }
    for (int i = tid; i < 1568; i += 512) rs[i] = rel[i];
    __syncthreads();

    float sa=0.f, qa=0.f, sb2=0.f, qb2=0.f, sc2=0.f, qc2=0.f;
    float4* ob4 = (float4*)(g_stk + blockIdx.x * 2500);
    for (int e = tid; e < 625; e += 512) {
        int i = e/25, j = e - i*25;
        float a=0.f, b=0.f, c2=0.f;
        int di = i - j + 24, dj = j - i + 24;
#pragma unroll
        for (int c = 0; c < 16; c++) {
            float qv = qs[c*25 + i], kv = ks[c*25 + j];
            a  += qv * kv;
            b  += qv * rs[c*49 + di];
            c2 += kv * rs[(16+c)*49 + dj];
        }
        ob4[e] = make_float4(a, b, c2, 0.f);
        sa += a; qa += a*a; sb2 += b; qb2 += b*b; sc2 += c2; qc2 += c2*c2;
    }
#pragma unroll
    for (int d = 16; d > 0; d >>= 1) {
        sa  += __shfl_xor_sync(0xffffffffu, sa,  d);
        qa  += __shfl_xor_sync(0xffffffffu, qa,  d);
        sb2 += __shfl_xor_sync(0xffffffffu, sb2, d);
        qb2 += __shfl_xor_sync(0xffffffffu, qb2, d);
        sc2 += __shfl_xor_sync(0xffffffffu, sc2, d);
        qc2 += __shfl_xor_sync(0xffffffffu, qc2, d);
    }
    if ((tid & 31) == 0) {
        atomicAdd(&ssum[0], sa);  atomicAdd(&ssq[0], qa);
        atomicAdd(&ssum[1], sb2); atomicAdd(&ssq[1], qb2);
        atomicAdd(&ssum[2], sc2); atomicAdd(&ssq[2], qc2);
    }
    __syncthreads();
    if (tid < 3) { atomicAdd(&g_ssum[tid*8 + g], ssum[tid]); atomicAdd(&g_ssq[tid*8 + g], ssq[tid]); }
}

// ---------------- K6: softmax + sv/sve; conflict-free transposed fills ----------
__global__ void __launch_bounds__(512) k6_attn(const float* __restrict__ rel,
                                               const float* __restrict__ qg,
                                               const float* __restrict__ qbb,
                                               const float* __restrict__ sg,
                                               const float* __restrict__ sbb) {
    __shared__ float sim[25*27];                   // stride 27: gcd(27,32)=1
    __shared__ __align__(16) float vs_t[25*32];    // [j][c]
    __shared__ __align__(16) float rv_t[49*32];    // [d][c]
    __shared__ float rinv[25];
    __shared__ float svsh[800], sesh[800];
    __shared__ float vsc[32], vbi[32], ssc[3], sbi[3];
    int tid = threadIdx.x;
    int n = blockIdx.x >> 3, g = blockIdx.x & 7;
    int gb = g * 64;

    if (tid < 32) {                                 // BN finalize for 32 v channels
        int ch = gb + 32 + tid;
        float m = g_qsum[ch] * (1.f/1600.f);
        float var = g_qsq[ch] * (1.f/1600.f) - m*m;
        float s = rsqrtf(var + EPSV) * qg[ch];
        vsc[tid] = s; vbi[tid] = qbb[ch] - m*s;
    } else if (tid < 35) {                          // sim BN finalize (3 channels)
        int t2 = tid - 32, ch = t2*8 + g;
        float m = g_ssum[ch] * (1.f/40000.f);
        float var = g_ssq[ch] * (1.f/40000.f) - m*m;
        float s = rsqrtf(var + EPSV) * sg[ch];
        ssc[t2] = s; sbi[t2] = sbb[ch] - m*s;
    }
    __syncthreads();

    // transposed fills: c = i&31 fast -> consecutive STS addresses (no conflicts)
    const float* qkvb = g_qkv + n*12800 + (gb + 32)*25;
    for (int i = tid; i < 800; i += 512) {          // 800 = 25*32
        int j = i >> 5, c = i & 31;
        vs_t[j*32 + c] = qkvb[c*25 + j]*vsc[c] + vbi[c];
    }
    const float* relv = rel + 32*49;
    for (int i = tid; i < 1568; i += 512) {         // 1568 = 49*32
        int d = i >> 5, c = i & 31;
        rv_t[d*32 + c] = relv[c*49 + d];
    }

    // single exp pass; BN'd logits are O(few sigma) so no max shift needed
    const float4* sb4 = (const float4*)(g_stk + blockIdx.x * 2500);
    for (int e = tid; e < 625; e += 512) {
        int i = e/25, j = e - i*25;
        float4 t = sb4[e];
        float s = t.x*ssc[0] + sbi[0] + t.y*ssc[1] + sbi[1] + t.z*ssc[2] + sbi[2];
        sim[i*27 + j] = __expf(s);
    }
    __syncthreads();
    if (tid < 25) {                                 // serial row sums (no atomics)
        float s = 0.f;
#pragma unroll
        for (int j = 0; j < 25; j++) s += sim[tid*27 + j];
        rinv[tid] = 1.f / s;
    }
    __syncthreads();

    // 400 work items: (cpair 0..15, i 0..24); stage results in smem only
    if (tid < 400) {
        int cp = tid & 15, i = tid >> 4;
        float sv0=0.f, sv1=0.f, se0=0.f, se1=0.f;
#pragma unroll
        for (int j = 0; j < 25; j++) {
            float wv = sim[i*27 + j];
            float2 v = ((const float2*)(vs_t + j*32))[cp];
            float2 r = ((const float2*)(rv_t + (i - j + 24)*32))[cp];
            sv0 += wv*v.x; sv1 += wv*v.y;
            se0 += wv*r.x; se1 += wv*r.y;
        }
        float ri = rinv[i];
        sv0 *= ri; sv1 *= ri; se0 *= ri; se1 *= ri;
        int c0 = 2*cp, c1 = c0 + 1;
        svsh[c0*25 + i] = sv0; sesh[c0*25 + i] = se0;
        svsh[c1*25 + i] = sv1; sesh[c1*25 + i] = se1;
    }
    __syncthreads();
    // coalesced float2 stores: cout = g*32 + c, idx = c*25 + i
    {
        float2* sob2 = g_so2 + (n*256 + g*32)*25;
        for (int idx = tid; idx < 800; idx += 512)
            sob2[idx] = make_float2(svsh[idx], sesh[idx]);
    }
    if (tid < 64) {
        int c = tid >> 1;
        const float* src = (tid & 1) ? (sesh + c*25) : (svsh + c*25);
        float s = 0.f, sq = 0.f;
#pragma unroll
        for (int i = 0; i < 25; i++) { float v = src[i]; s += v; sq += v*v; }
        atomicAdd(&g_osum[gb + tid], s);
        atomicAdd(&g_osq[gb + tid], sq);
    }
}

// ---------------- K8: out = x*(1+sigmoid(o));  ldcs/stcs, 16-deep load batch ----
__global__ void __launch_bounds__(400) k8_out(const float* __restrict__ x,
                                              float* __restrict__ out,
                                              const float* __restrict__ og,
                                              const float* __restrict__ ob) {
    __shared__ float msh[16][25];
    int tid = threadIdx.x;
    int sg = tid / 100, p = tid % 100;
    int base = blockIdx.x * 16 + sg;               // this group's slabs: base+4w, w=0..3
    {   // gate: 400 threads <-> 16 slabs x 25 lanes, exactly one each
        int w = p / 25, pv = p % 25;
        int slab = base + 4*w;
        int n = slab >> 8, c = slab & 255;
        int ch0 = 2*c, ch1 = ch0 + 1;
        float m0 = g_osum[ch0] * (1.f/1600.f);
        float v0 = g_osq[ch0] * (1.f/1600.f) - m0*m0;
        float sc0 = rsqrtf(v0 + EPSV) * og[ch0];
        float b0 = ob[ch0] - m0*sc0;
        float m1 = g_osum[ch1] * (1.f/1600.f);
        float v1 = g_osq[ch1] * (1.f/1600.f) - m1*m1;
        float sc1 = rsqrtf(v1 + EPSV) * og[ch1];
        float b1 = ob[ch1] - m1*sc1;
        float2 t2 = g_so2[(n*256 + c)*25 + pv];
        float t = (t2.x*sc0 + b0) + (t2.y*sc1 + b1);
        msh[sg*4 + w][pv] = 1.f + 1.f/(1.f + expf(-t));
    }
    __syncthreads();
    int f0 = 4*p;
    int i0 = f0 % 25, i1 = (f0+1) % 25, i2 = (f0+2) % 25, i3 = (f0+3) % 25;
    const float4* pa = (const float4*)(x + (base +  0)*1600) + p;
    const float4* pb = (const float4*)(x + (base +  4)*1600) + p;
    const float4* pc = (const float4*)(x + (base +  8)*1600) + p;
    const float4* pd = (const float4*)(x + (base + 12)*1600) + p;
    float4 a0=__ldcs(pa),a1=__ldcs(pa+100),a2=__ldcs(pa+200),a3=__ldcs(pa+300);
    float4 b0=__ldcs(pb),b1=__ldcs(pb+100),b2=__ldcs(pb+200),b3=__ldcs(pb+300);
    float4 c0=__ldcs(pc),c1=__ldcs(pc+100),c2=__ldcs(pc+200),c3=__ldcs(pc+300);
    float4 d0=__ldcs(pd),d1=__ldcs(pd+100),d2=__ldcs(pd+200),d3=__ldcs(pd+300);
    const float* mA = msh[sg*4 + 0];
    const float* mB = msh[sg*4 + 1];
    const float* mC = msh[sg*4 + 2];
    const float* mD = msh[sg*4 + 3];
    float A0=mA[i0],A1=mA[i1],A2=mA[i2],A3=mA[i3];
    float B0=mB[i0],B1=mB[i1],B2=mB[i2],B3=mB[i3];
    float C0=mC[i0],C1=mC[i1],C2=mC[i2],C3=mC[i3];
    float D0=mD[i0],D1=mD[i1],D2=mD[i2],D3=mD[i3];
    float4* oa = (float4*)(out + (base +  0)*1600) + p;
    float4* obp= (float4*)(out + (base +  4)*1600) + p;
    float4* oc = (float4*)(out + (base +  8)*1600) + p;
    float4* od = (float4*)(out + (base + 12)*1600) + p;
    __stcs(oa,     make_float4(a0.x*A0, a0.y*A1, a0.z*A2, a0.w*A3));
    __stcs(oa+100, make_float4(a1.x*A0, a1.y*A1, a1.z*A2, a1.w*A3));
    __stcs(oa+200, make_float4(a2.x*A0, a2.y*A1, a2.z*A2, a2.w*A3));
    __stcs(oa+300, make_float4(a3.x*A0, a3.y*A1, a3.z*A2, a3.w*A3));
    __stcs(obp,     make_float4(b0.x*B0, b0.y*B1, b0.z*B2, b0.w*B3));
    __stcs(obp+100, make_float4(b1.x*B0, b1.y*B1, b1.z*B2, b1.w*B3));
    __stcs(obp+200, make_float4(b2.x*B0, b2.y*B1, b2.z*B2, b2.w*B3));
    __stcs(obp+300, make_float4(b3.x*B0, b3.y*B1, b3.z*B2, b3.w*B3));
    __stcs(oc,     make_float4(c0.x*C0, c0.y*C1, c0.z*C2, c0.w*C3));
    __stcs(oc+100, make_float4(c1.x*C0, c1.y*C1, c1.z*C2, c1.w*C3));
    __stcs(oc+200, make_float4(c2.x*C0, c2.y*C1, c2.z*C2, c2.w*C3));
    __stcs(oc+300, make_float4(c3.x*C0, c3.y*C1, c3.z*C2, c3.w*C3));
    __stcs(od,     make_float4(d0.x*D0, d0.y*D1, d0.z*D2, d0.w*D3));
    __stcs(od+100, make_float4(d1.x*D0, d1.y*D1, d1.z*D2, d1.w*D3));
    __stcs(od+200, make_float4(d2.x*D0, d2.y*D1, d2.z*D2, d2.w*D3));
    __stcs(od+300, make_float4(d3.x*D0, d3.y*D1, d3.z*D2, d3.w*D3));
}

// ---------------- launch ---------------------------------------------------------
extern "C" void kernel_launch(void* const* d_in, const int* in_sizes, int n_in,
                              void* d_out, int out_size) {
    const float* x   = (const float*)d_in[0];
    const float* w   = (const float*)d_in[1];
    const float* rel = (const float*)d_in[2];
    const float* qg  = (const float*)d_in[3];
    const float* qb  = (const float*)d_in[4];
    const float* sg  = (const float*)d_in[5];
    const float* sbb = (const float*)d_in[6];
    const float* og  = (const float*)d_in[7];
    const float* ob  = (const float*)d_in[8];
    float* out = (float*)d_out;

    k1_mean<<<1024, 400>>>(x);
    k2_qkv<<<512, 256>>>(w);
    k4_sim<<<512, 512>>>(rel, qg, qb);
    k6_attn<<<512, 512>>>(rel, qg, qb, sg, sbb);
    k8_out<<<1024, 400>>>(x, out, og, ob);
}